// round 17
// baseline (speedup 1.0000x reference)
#include <cuda_runtime.h>
#include <cstdint>

// Problem constants
#define SIN   512          // input H=W
#define HW    128          // resized H=W and volume H=W
#define ND    128          // depth bins
#define NB    8            // batch

// Scratch: per-pixel {xray_resized, (float)d_idx}
__device__ float2 g_pix[NB * HW * HW];

// ---------------------------------------------------------------------------
// Kernel A: jax.image.resize(bilinear, antialias) 512->128 for both arrays,
// fused with d_idx computation.
// R17: OOB guards replaced with clamped addresses + zero weights so all 16
// LDG.128s batch (full MLP). Arithmetic identical (0-weight FMA adds 0).
// ---------------------------------------------------------------------------
__global__ __launch_bounds__(128) void resize_kernel(
    const float* __restrict__ depth, const float* __restrict__ xray)
{
    __shared__ float2 hrow[SIN];   // H-contracted row at this output row: {d, x}

    const int ho  = blockIdx.x;    // 0..127
    const int b   = blockIdx.y;    // 0..7
    const int tid = threadIdx.x;   // 128 threads

    const float BW[8] = {0.125f, 0.375f, 0.625f, 0.875f,
                         0.875f, 0.625f, 0.375f, 0.125f};

    const int ih0 = 4 * ho - 2;

    float whn[8]; float hs = 0.f;
    #pragma unroll
    for (int k = 0; k < 8; k++) {
        int ih = ih0 + k;
        float w = (ih >= 0 && ih < SIN) ? BW[k] : 0.f;
        whn[k] = w; hs += w;
    }
    #pragma unroll
    for (int k = 0; k < 8; k++) whn[k] = __fdiv_rn(whn[k], hs);

    const float* dbase = depth + (size_t)b * SIN * SIN;
    const float* xbase = xray  + (size_t)b * SIN * SIN;

    {
        const int c0 = tid * 4;
        float4 ad = make_float4(0.f, 0.f, 0.f, 0.f);
        float4 ax = make_float4(0.f, 0.f, 0.f, 0.f);
        #pragma unroll
        for (int kh = 0; kh < 8; kh++) {
            const int ih = min(max(ih0 + kh, 0), SIN - 1);  // clamped addr
            const float4 dv = *(const float4*)(dbase + (size_t)ih * SIN + c0);
            const float4 xv = *(const float4*)(xbase + (size_t)ih * SIN + c0);
            const float w = whn[kh];                         // 0 for OOB rows
            ad.x = fmaf(w, dv.x, ad.x); ad.y = fmaf(w, dv.y, ad.y);
            ad.z = fmaf(w, dv.z, ad.z); ad.w = fmaf(w, dv.w, ad.w);
            ax.x = fmaf(w, xv.x, ax.x); ax.y = fmaf(w, xv.y, ax.y);
            ax.z = fmaf(w, xv.z, ax.z); ax.w = fmaf(w, xv.w, ax.w);
        }
        hrow[c0 + 0] = make_float2(ad.x, ax.x);
        hrow[c0 + 1] = make_float2(ad.y, ax.y);
        hrow[c0 + 2] = make_float2(ad.z, ax.z);
        hrow[c0 + 3] = make_float2(ad.w, ax.w);
    }
    __syncthreads();

    const int wo  = tid;
    const int iw0 = 4 * wo - 2;

    float wwn[8]; float ws = 0.f;
    #pragma unroll
    for (int k = 0; k < 8; k++) {
        int iw = iw0 + k;
        float w = (iw >= 0 && iw < SIN) ? BW[k] : 0.f;
        wwn[k] = w; ws += w;
    }
    #pragma unroll
    for (int k = 0; k < 8; k++) wwn[k] = __fdiv_rn(wwn[k], ws);

    float ad = 0.f, ax = 0.f;
    #pragma unroll
    for (int k = 0; k < 8; k++) {
        const int iw = min(max(iw0 + k, 0), SIN - 1);        // clamped addr
        float2 p = hrow[iw];
        ad = fmaf(wwn[k], p.x, ad);
        ax = fmaf(wwn[k], p.y, ax);
    }

    // d_idx = clip(int32((d/100)*127), 0, 127) — IEEE ops to match reference
    float nd = __fdiv_rn(ad, 100.0f);
    int di = (int)__fmul_rn(nd, 127.0f);
    di = min(max(di, 0), ND - 1);

    g_pix[((size_t)b * HW + ho) * HW + wo] = make_float2(ax, (float)di);
}

// ---------------------------------------------------------------------------
// Kernel B (R17): pure gather, clamped-quartic profile, scalar math,
// neighbors read from smem INSIDE live iterations (no register cache)
// + __launch_bounds__(256,6): regs <=40 -> 6 blocks/SM (~62% occ).
//   out[b,d,h,w] = sum over 3x3 nbhd of x_n * C(|d - di_n|)
//   C = quartic exact at a=0..3, C(4)=0, evaluated at a=min(|d-di|,4).
// Rows d=0/d=127 use the edge quartic (box tap outside volume dropped) via
// selected coefficients — exact for any input, no fallback path.
// ---------------------------------------------------------------------------
__global__ __launch_bounds__(256, 6) void gather_pool_kernel(float* __restrict__ out)
{
    __shared__ float2 pix[180];     // 10x18 halo {x, d_idx}
    __shared__ int    srange[2];    // [0]=min di, [1]=max di

    const int tid = threadIdx.x;    // 0..255
    const int w0  = blockIdx.x * 16;
    const int h0  = blockIdx.y * 8;
    const int b   = blockIdx.z;

    // Interior quartic: C(a) exact at a=0..3, C(4)=0 (C = box3(gauss5)/27)
    const float K4f = -0.0013033148265782292f;
    const float K3f =  0.013512938242255463f;
    const float K2f = -0.04120828915412581f;
    const float K1f =  0.011546985128225586f;
    const float K0f =  0.08196523405278766f;
    // Edge quartic (d==0 or d==127): one box tap dropped
    const float E4f = -0.001403915948130981f;
    const float E3f =  0.015354352440725033f;
    const float E2f = -0.05224795525495059f;
    const float E1f =  0.03829751876235654f;
    const float E0f =  0.05950113554491235f;

    const float4 z4 = make_float4(0.f, 0.f, 0.f, 0.f);

    // Mapping: lane g -> column quad, warp -> depth phase (d == dwarp mod 8)
    const int g     = tid & 31;     // quad index 0..31
    const int dwarp = tid >> 5;     // 0..7
    const int qh    = g >> 2;       // 0..7   (h within tile)
    const int qw4   = (g & 3) * 4;  // 0,4,8,12 (first w of quad)

    // Phase A: stage halo pixels; init range.
    float2 q = make_float2(0.f, 64.f);
    bool valid = false;
    if (tid < 180) {
        const int ph = h0 + tid / 18 - 1;
        const int pw = w0 + tid % 18 - 1;
        if (ph >= 0 && ph < HW && pw >= 0 && pw < HW) {
            q = g_pix[((size_t)b * HW + ph) * HW + pw];
            valid = true;
        }
        pix[tid] = q;
    }
    if (tid == 0) { srange[0] = ND - 1; srange[1] = 0; }
    __syncthreads();

    // Phase B: min/max over valid halo d_idx.
    if (valid) {
        const int di = (int)q.y;
        atomicMin(&srange[0], di);
        atomicMax(&srange[1], di);
    }
    __syncthreads();

    const int smin = srange[0], smax = srange[1];
    const int olo  = max(0, smin - 3);
    const int ohi  = min(ND - 1, smax + 3);

    const float2* prow = &pix[qh * 18 + qw4];   // this quad's halo base

    const size_t obase =
        (size_t)b * ND * HW * HW + (size_t)(h0 + qh) * HW + (w0 + qw4);

    #pragma unroll
    for (int i = 0; i < 16; i++) {
        const int d = dwarp + 8 * i;            // warp-uniform depth
        float4 o = z4;
        if (d >= olo && d <= ohi) {             // warp-uniform branch
            const bool edge = (d == 0) | (d == ND - 1);
            const float c4 = edge ? E4f : K4f;
            const float c3 = edge ? E3f : K3f;
            const float c2 = edge ? E2f : K2f;
            const float c1 = edge ? E1f : K1f;
            const float c0 = edge ? E0f : K0f;
            const float df = (float)d;

            float s[6];
            #pragma unroll
            for (int c = 0; c < 6; c++) {
                float acc = 0.f;
                #pragma unroll
                for (int r = 0; r < 3; r++) {
                    const float2 qq = prow[r * 18 + c];      // LDS.64
                    const float a = fminf(fabsf(df - qq.y), 4.0f);
                    float p = fmaf(a, c4, c3);
                    p = fmaf(a, p, c2);
                    p = fmaf(a, p, c1);
                    p = fmaf(a, p, c0);
                    acc = fmaf(qq.x, p, acc);
                }
                s[c] = acc;
            }
            o.x = s[0] + s[1] + s[2];
            o.y = s[1] + s[2] + s[3];
            o.z = s[2] + s[3] + s[4];
            o.w = s[3] + s[4] + s[5];
        }
        *(float4*)&out[obase + (size_t)d * HW * HW] = o;
    }
}

// ---------------------------------------------------------------------------
extern "C" void kernel_launch(void* const* d_in, const int* in_sizes, int n_in,
                              void* d_out, int out_size)
{
    const float* depth = (const float*)d_in[0];
    const float* xray  = (const float*)d_in[1];
    float* out = (float*)d_out;

    // Kernel A: resize + d_idx (clamped unconditional loads, full MLP)
    resize_kernel<<<dim3(HW, NB), 128>>>(depth, xray);

    // Kernel B: pure-gather splat + 3x3x3 box average (quartic, high occ)
    gather_pool_kernel<<<dim3(HW / 16, HW / 8, NB), 256>>>(out);
}